// round 7
// baseline (speedup 1.0000x reference)
#include <cuda_runtime.h>
#include <cuda_bf16.h>
#include <math.h>
#include <stdint.h>

// ---------------- problem constants ----------------
#define NN 4096
#define DD 256
#define HH 8
#define HD 32
#define EE 65536
#define NWORDS 128
// (1/sqrt(32)) * log2(e): folded into Q so softmax weight = exp2(S)
#define QSCALE 0.25503486f

// ---------------- scratch globals (no allocs allowed) ----------------
__device__ uint32_t g_adj[NN * NWORDS];
__device__ uint32_t g_mask[NN * NWORDS];
__device__ __nv_bfloat16 g_xb[NN * DD];
__device__ __nv_bfloat16 g_Wb[4 * DD * DD];   // Wq, Wk, Wv, Wo (bf16)
__device__ uint8_t g_Qf8[NN * DD];            // e4m3, pre-scaled by QSCALE
__device__ uint8_t g_Kf8[NN * DD];            // e4m3
__device__ __nv_bfloat16 g_Vb[NN * DD];
__device__ __nv_bfloat16 g_attb[NN * DD];     // attention output (bf16)
__device__ float g_tmp[NN * DD];

// ---------------- PTX helpers ----------------
__device__ __forceinline__ uint32_t smem_u32(const void* p) {
    uint32_t a;
    asm("{ .reg .u64 t; cvta.to.shared.u64 t, %1; cvt.u32.u64 %0, t; }"
        : "=r"(a) : "l"(p));
    return a;
}
__device__ __forceinline__ uint32_t pack_bf16x2(float lo, float hi) {
    uint32_t r;
    asm("cvt.rn.bf16x2.f32 %0, %1, %2;" : "=r"(r) : "f"(hi), "f"(lo));
    return r;
}
__device__ __forceinline__ uint16_t pack_e4m3x2(float lo, float hi) {
    uint16_t r;
    asm("cvt.rn.satfinite.e4m3x2.f32 %0, %1, %2;" : "=h"(r) : "f"(hi), "f"(lo));
    return r;
}
__device__ __forceinline__ uint32_t ex2_bf16x2(uint32_t x) {
    uint32_t y;
    asm("ex2.approx.ftz.bf16x2 %0, %1;" : "=r"(y) : "r"(x));
    return y;
}
__device__ __forceinline__ void ldsm_x4(uint32_t* r, uint32_t addr) {
    asm volatile("ldmatrix.sync.aligned.m8n8.x4.shared.b16 {%0,%1,%2,%3}, [%4];"
        : "=r"(r[0]), "=r"(r[1]), "=r"(r[2]), "=r"(r[3]) : "r"(addr));
}
__device__ __forceinline__ void ldsm_x2(uint32_t* r, uint32_t addr) {
    asm volatile("ldmatrix.sync.aligned.m8n8.x2.shared.b16 {%0,%1}, [%2];"
        : "=r"(r[0]), "=r"(r[1]) : "r"(addr));
}
__device__ __forceinline__ void ldsm_x4_t(uint32_t* r, uint32_t addr) {
    asm volatile("ldmatrix.sync.aligned.m8n8.x4.trans.shared.b16 {%0,%1,%2,%3}, [%4];"
        : "=r"(r[0]), "=r"(r[1]), "=r"(r[2]), "=r"(r[3]) : "r"(addr));
}
__device__ __forceinline__ void mma_bf16(float* c, const uint32_t* a, const uint32_t* b) {
    asm volatile(
        "mma.sync.aligned.m16n8k16.row.col.f32.bf16.bf16.f32 "
        "{%0,%1,%2,%3}, {%4,%5,%6,%7}, {%8,%9}, {%0,%1,%2,%3};"
        : "+f"(c[0]), "+f"(c[1]), "+f"(c[2]), "+f"(c[3])
        : "r"(a[0]), "r"(a[1]), "r"(a[2]), "r"(a[3]), "r"(b[0]), "r"(b[1]));
}
__device__ __forceinline__ void mma_fp8(float* c, const uint32_t* a, const uint32_t* b) {
    asm volatile(
        "mma.sync.aligned.m16n8k32.row.col.f32.e4m3.e4m3.f32 "
        "{%0,%1,%2,%3}, {%4,%5,%6,%7}, {%8,%9}, {%0,%1,%2,%3};"
        : "+f"(c[0]), "+f"(c[1]), "+f"(c[2]), "+f"(c[3])
        : "r"(a[0]), "r"(a[1]), "r"(a[2]), "r"(a[3]), "r"(b[0]), "r"(b[1]));
}
__device__ __forceinline__ void cp16(uint32_t dst, const void* src) {
    asm volatile("cp.async.cg.shared.global [%0], [%1], 16;" :: "r"(dst), "l"(src));
}
#define CP_COMMIT() asm volatile("cp.async.commit_group;" ::: "memory")
#define CP_WAIT(n)  asm volatile("cp.async.wait_group %0;" :: "n"(n) : "memory")

// ================= 0. bf16 casts (x + 4 weights, one launch) =================
__global__ void cast_kernel(const float* __restrict__ x,
                            const float* __restrict__ Wq, const float* __restrict__ Wk,
                            const float* __restrict__ Wv, const float* __restrict__ Wo) {
    int i = (blockIdx.x * 256 + threadIdx.x) * 4;
    const float* src;
    __nv_bfloat16* dst;
    if (i < NN * DD) {
        src = x + i; dst = g_xb + i;
    } else {
        int j = i - NN * DD;
        int w = j >> 16;
        int o = j & 65535;
        src = ((w == 0) ? Wq : (w == 1) ? Wk : (w == 2) ? Wv : Wo) + o;
        dst = g_Wb + w * (DD * DD) + o;
    }
    float4 v = *(const float4*)src;
    *(uint2*)dst = make_uint2(pack_bf16x2(v.x, v.y), pack_bf16x2(v.z, v.w));
}

// ================= 1. adjacency init (zero + self loops) =================
__global__ void adj_init_kernel() {
    int idx = blockIdx.x * blockDim.x + threadIdx.x;
    int n = idx >> 7, w = idx & 127;
    uint32_t v = 0;
    if (w == (n >> 5)) v = 1u << (n & 31);
    g_adj[idx] = v;
}

// ================= 2. scatter edges (undirected) =================
__global__ void edge_kernel(const int* __restrict__ ei) {
    int e = blockIdx.x * blockDim.x + threadIdx.x;
    if (e >= EE) return;
    int s = ei[e], d = ei[EE + e];
    atomicOr(&g_adj[s * NWORDS + (d >> 5)], 1u << (d & 31));
    atomicOr(&g_adj[d * NWORDS + (s >> 5)], 1u << (s & 31));
}

// ================= 3. reach-2 mask (neighbor-list, MLP-unrolled) =========
__global__ void mask_kernel() {
    int n = blockIdx.x;
    int tid = threadIdx.x;  // 128
    __shared__ uint16_t nbr[1024];
    __shared__ int cnt;
    if (tid == 0) cnt = 0;
    __syncthreads();
    uint32_t bits = g_adj[n * NWORDS + tid];
    while (bits) {
        int b = __ffs(bits) - 1;
        bits &= bits - 1;
        int i = atomicAdd(&cnt, 1);
        nbr[i] = (uint16_t)((tid << 5) + b);
    }
    __syncthreads();
    int c = cnt;
    uint32_t acc = 0;
    int i = 0;
    for (; i + 4 <= c; i += 4) {
        uint32_t a0 = g_adj[(int)nbr[i + 0] * NWORDS + tid];
        uint32_t a1 = g_adj[(int)nbr[i + 1] * NWORDS + tid];
        uint32_t a2 = g_adj[(int)nbr[i + 2] * NWORDS + tid];
        uint32_t a3 = g_adj[(int)nbr[i + 3] * NWORDS + tid];
        acc |= (a0 | a1) | (a2 | a3);
    }
    for (; i < c; i++)
        acc |= g_adj[(int)nbr[i] * NWORDS + tid];
    g_mask[n * NWORDS + tid] = acc;
}

// ================= 4. bf16 tensor-core GEMM =================
// C[M=4096, N=256] = A[4096,256]@W[256,256] + bias. CTA tile 64x128, BK=32.
// mode: 0 = bf16 out, 1 = fp32 out, 2 = e4m3 out
__device__ __forceinline__ void gemm_core(const __nv_bfloat16* __restrict__ A,
                                          const __nv_bfloat16* __restrict__ W,
                                          const float* __restrict__ bias,
                                          void* __restrict__ Cv, float scale, int mode) {
    __shared__ __nv_bfloat16 sA[2][64 * 40];
    __shared__ __nv_bfloat16 sB[2][32 * 136];

    const int tid = threadIdx.x;
    const int wid = tid >> 5;
    const int lane = tid & 31;
    const int m0 = blockIdx.y * 64;
    const int n0 = blockIdx.x * 128;

    const uint32_t aA = smem_u32(sA);
    const uint32_t aB = smem_u32(sB);
    const char* Abase = (const char*)A + (size_t)m0 * (DD * 2);
    const char* Bbase = (const char*)W + (size_t)n0 * 2;

    {
#pragma unroll
        for (int j = 0; j < 2; j++) {
            int t = tid + j * 128;
            int r = t >> 2, c = t & 3;
            cp16(aA + r * 80 + c * 16, Abase + (size_t)r * 512 + c * 16);
        }
#pragma unroll
        for (int j = 0; j < 4; j++) {
            int t = tid + j * 128;
            int r = t >> 4, c = t & 15;
            cp16(aB + r * 272 + c * 16, Bbase + (size_t)r * 512 + c * 16);
        }
        CP_COMMIT();
    }

    float acc[16][4];
#pragma unroll
    for (int j = 0; j < 16; j++)
        acc[j][0] = acc[j][1] = acc[j][2] = acc[j][3] = 0.f;

    const int m = lane >> 3, rr = lane & 7;
    const uint32_t a_off = (uint32_t)((wid * 16 + (m & 1) * 8 + rr) * 80 + (m >> 1) * 16);
    const uint32_t b_lane = (uint32_t)(((lane >> 3) & 1) * 8 * 272 + (lane & 7) * 272 +
                                       (lane >> 4) * 16);

    for (int t = 0; t < 8; t++) {
        if (t < 7) {
            int nb = (t + 1) & 1;
            uint32_t dA = aA + (uint32_t)nb * 5120;
            uint32_t dB = aB + (uint32_t)nb * 8704;
            const char* As = Abase + (size_t)(t + 1) * 64;
            const char* Bs = Bbase + (size_t)(t + 1) * 32 * 512;
#pragma unroll
            for (int j = 0; j < 2; j++) {
                int u = tid + j * 128;
                int r = u >> 2, c = u & 3;
                cp16(dA + r * 80 + c * 16, As + (size_t)r * 512 + c * 16);
            }
#pragma unroll
            for (int j = 0; j < 4; j++) {
                int u = tid + j * 128;
                int r = u >> 4, c = u & 15;
                cp16(dB + r * 272 + c * 16, Bs + (size_t)r * 512 + c * 16);
            }
            CP_COMMIT();
            CP_WAIT(1);
        } else {
            CP_WAIT(0);
        }
        __syncthreads();

        const uint32_t bufA = aA + (uint32_t)(t & 1) * 5120;
        const uint32_t bufB = aB + (uint32_t)(t & 1) * 8704;

        uint32_t aq[2][4];
        ldsm_x4(aq[0], bufA + a_off);
        ldsm_x4(aq[1], bufA + a_off + 32);

#pragma unroll
        for (int ks = 0; ks < 2; ks++) {
#pragma unroll
            for (int j = 0; j < 8; j++) {
                uint32_t vb[4];
                ldsm_x4_t(vb, bufB + (uint32_t)(ks * 16 * 272 + j * 32) + b_lane);
                mma_bf16(acc[2 * j],     aq[ks], vb);
                mma_bf16(acc[2 * j + 1], aq[ks], vb + 2);
            }
        }
        __syncthreads();
    }

    const int gg = lane >> 2, tig = lane & 3;
    const int r0 = m0 + wid * 16 + gg;
#pragma unroll
    for (int j = 0; j < 16; j++) {
        int col = n0 + j * 8 + 2 * tig;
        float2 b2 = __ldg((const float2*)(bias + col));
        if (mode == 1) {
            float* Cf = (float*)Cv;
            *(float2*)(Cf + (size_t)r0 * DD + col) =
                make_float2(acc[j][0] + b2.x, acc[j][1] + b2.y);
            *(float2*)(Cf + (size_t)(r0 + 8) * DD + col) =
                make_float2(acc[j][2] + b2.x, acc[j][3] + b2.y);
        } else if (mode == 0) {
            __nv_bfloat16* Cb = (__nv_bfloat16*)Cv;
            *(uint32_t*)(Cb + (size_t)r0 * DD + col) =
                pack_bf16x2(acc[j][0] + b2.x, acc[j][1] + b2.y);
            *(uint32_t*)(Cb + (size_t)(r0 + 8) * DD + col) =
                pack_bf16x2(acc[j][2] + b2.x, acc[j][3] + b2.y);
        } else {
            uint8_t* C8 = (uint8_t*)Cv;
            *(uint16_t*)(C8 + (size_t)r0 * DD + col) =
                pack_e4m3x2((acc[j][0] + b2.x) * scale, (acc[j][1] + b2.y) * scale);
            *(uint16_t*)(C8 + (size_t)(r0 + 8) * DD + col) =
                pack_e4m3x2((acc[j][2] + b2.x) * scale, (acc[j][3] + b2.y) * scale);
        }
    }
}

__global__ void __launch_bounds__(128) qkv_gemm_kernel(const float* __restrict__ bq,
                                                       const float* __restrict__ bk,
                                                       const float* __restrict__ bv) {
    int z = blockIdx.z;
    const float* bias = (z == 0) ? bq : (z == 1) ? bk : bv;
    void* C = (z == 0) ? (void*)g_Qf8 : (z == 1) ? (void*)g_Kf8 : (void*)g_Vb;
    float scale = (z == 0) ? QSCALE : 1.f;
    int mode = (z == 2) ? 0 : 2;
    gemm_core(g_xb, g_Wb + (size_t)z * DD * DD, bias, C, scale, mode);
}
__global__ void __launch_bounds__(128) wo_gemm_kernel(const float* __restrict__ bo) {
    gemm_core(g_attb, g_Wb + (size_t)3 * DD * DD, bo, g_tmp, 1.f, 1);
}

// ================= 5. mma.sync attention (fp8 QK^T, bf16 PV) =================
// CTA: 256 threads (8 warps), 128 queries, one head. 32 kv tiles of 128 keys.
// Q/K: e4m3, rows 32B data padded to 48B stride (conflict-free ldmatrix).
// QK^T: m16n8k32 e4m3 (HD=32 -> ONE MMA per 8 keys).
// PV: m16n8k16 bf16 as before; P packed in-register.
struct __align__(16) AttnSmem3 {
    uint8_t Qs[128 * 48];             // 6144 B
    uint8_t Ks[2][128 * 48];          // 2 x 6144 B
    __nv_bfloat16 Vs[2][128 * 40];    // 2 x 10240 B
};                                    // 39 KB

__global__ void __launch_bounds__(256, 2) attn_kernel() {
    __shared__ AttnSmem3 sm;
    const int tid = threadIdx.x;
    const int wid = tid >> 5;        // 0..7
    const int lane = tid & 31;
    const int h = blockIdx.y;
    const int q0 = blockIdx.x * 128;

    const uint32_t s_q = smem_u32(sm.Qs);
    const uint32_t s_k0 = smem_u32(sm.Ks[0]);
    const uint32_t s_v0 = smem_u32(sm.Vs[0]);

    const char* ksrc = (const char*)(g_Kf8 + h * HD);        // fp8 rows: 256B
    const char* vsrc = (const char*)(g_Vb + h * HD);          // bf16 rows: 512B

    // ---- prologue: Q + K0/V0 via cp.async ----
    {
        const char* qsrc = (const char*)(g_Qf8 + (size_t)q0 * DD + h * HD);
        {   // Q: 128 rows x 32B = 256 chunks, 1/thread
            int r = tid >> 1, c = tid & 1;
            cp16(s_q + (uint32_t)(r * 48 + c * 16), qsrc + (size_t)r * 256 + c * 16);
        }
        {   // K0: 256 chunks, 1/thread
            int r = tid >> 1, c = tid & 1;
            cp16(s_k0 + (uint32_t)(r * 48 + c * 16), ksrc + (size_t)r * 256 + c * 16);
        }
#pragma unroll
        for (int j = 0; j < 2; j++) {   // V0: 512 chunks, 2/thread
            int chunk = tid + j * 256;
            int r = chunk >> 2, c = chunk & 3;
            cp16(s_v0 + (uint32_t)(r * 80 + c * 16), vsrc + (size_t)r * 512 + c * 16);
        }
        CP_COMMIT();
    }

    const int wq0 = wid * 16;
    const int g = lane >> 2, tig = lane & 3;
    const int row0 = q0 + wq0 + g;

    uint4 mw_lo = *(const uint4*)(g_mask + (size_t)row0 * NWORDS);
    uint4 mw_hi = *(const uint4*)(g_mask + (size_t)(row0 + 8) * NWORDS);

    CP_WAIT(0);
    __syncthreads();

    // ---- Q fragment (fp8 A, m16n8k32): one ldsm_x4 over 16 rows x 32B ----
    uint32_t aq[4];
    {
        int m = lane >> 3, rr = lane & 7;
        uint32_t base = s_q + (uint32_t)((wq0 + (m & 1) * 8 + rr) * 48 + (m >> 1) * 16);
        ldsm_x4(aq, base);
    }

    float o[4][4];
#pragma unroll
    for (int v = 0; v < 4; v++)
#pragma unroll
        for (int i = 0; i < 4; i++) o[v][i] = 0.f;
    float ls0 = 0.f, ls1 = 0.f;

    // K b-frag lane offset: lanes 0-7 -> rows, byte 0; lanes 8-15 -> byte 16
    const uint32_t koff = (uint32_t)((lane & 7) * 48 + ((lane >> 3) & 1) * 16);
    const uint32_t v_lane_off = (uint32_t)(((lane >> 3) & 1) * 8 * 80 + (lane & 7) * 80 +
                                           (lane >> 4) * 16);

    for (int t = 0; t < 32; t++) {
        int buf = t & 1;
        uint4 mw_lo_n, mw_hi_n;
        if (t < 31) {
            mw_lo_n = *(const uint4*)(g_mask + (size_t)row0 * NWORDS + (t + 1) * 4);
            mw_hi_n = *(const uint4*)(g_mask + (size_t)(row0 + 8) * NWORDS + (t + 1) * 4);
            int nb = (t + 1) & 1;
            uint32_t skb = s_k0 + (uint32_t)nb * 6144;
            uint32_t svb = s_v0 + (uint32_t)nb * 10240;
            {   // K: 1 chunk/thread
                int r = tid >> 1, c = tid & 1;
                cp16(skb + (uint32_t)(r * 48 + c * 16),
                     ksrc + (size_t)(t + 1) * 128 * 256 + (size_t)r * 256 + c * 16);
            }
#pragma unroll
            for (int j = 0; j < 2; j++) {   // V: 2 chunks/thread
                int chunk = tid + j * 256;
                int r = chunk >> 2, c = chunk & 3;
                cp16(svb + (uint32_t)(r * 80 + c * 16),
                     vsrc + (size_t)(t + 1) * 128 * 512 + (size_t)r * 512 + c * 16);
            }
            CP_COMMIT();
            CP_WAIT(1);
        } else {
            CP_WAIT(0);
        }
        __syncthreads();

        const uint32_t kb_base = s_k0 + (uint32_t)buf * 6144;
        const uint32_t vb_base = s_v0 + (uint32_t)buf * 10240;
        const uint32_t mwl[4] = {mw_lo.x, mw_lo.y, mw_lo.z, mw_lo.w};
        const uint32_t mwh[4] = {mw_hi.x, mw_hi.y, mw_hi.z, mw_hi.w};

        uint32_t ap[8][4];
#pragma unroll
        for (int qd = 0; qd < 4; qd++) {
            uint32_t kb[4][2];
#pragma unroll
            for (int nt = 0; nt < 4; nt++)
                ldsm_x2(kb[nt], kb_base + (uint32_t)((qd * 4 + nt) * (8 * 48)) + koff);
            float c4[4][4];
#pragma unroll
            for (int nt = 0; nt < 4; nt++) {
                c4[nt][0] = c4[nt][1] = c4[nt][2] = c4[nt][3] = 0.f;
                mma_fp8(c4[nt], aq, kb[nt]);
            }
            uint32_t w0 = mwl[qd] >> (2 * tig);
            uint32_t w1 = mwh[qd] >> (2 * tig);
#pragma unroll
            for (int nt = 0; nt < 4; nt++) {
                uint32_t b0 = w0 >> (nt * 8), b1 = w1 >> (nt * 8);
                uint32_t m01 = ((b0 & 1u) ? 0x0000FFFFu : 0u) | ((b0 & 2u) ? 0xFFFF0000u : 0u);
                uint32_t m23 = ((b1 & 1u) ? 0x0000FFFFu : 0u) | ((b1 & 2u) ? 0xFFFF0000u : 0u);
                uint32_t p01 = ex2_bf16x2(pack_bf16x2(c4[nt][0], c4[nt][1])) & m01;
                uint32_t p23 = ex2_bf16x2(pack_bf16x2(c4[nt][2], c4[nt][3])) & m23;
                ls0 += __uint_as_float(p01 << 16) + __uint_as_float(p01 & 0xFFFF0000u);
                ls1 += __uint_as_float(p23 << 16) + __uint_as_float(p23 & 0xFFFF0000u);
                int nth = qd * 4 + nt;
                ap[nth >> 1][(nth & 1) * 2 + 0] = p01;
                ap[nth >> 1][(nth & 1) * 2 + 1] = p23;
            }
        }

        // ---- O += P @ V (bf16) ----
#pragma unroll
        for (int kt = 0; kt < 8; kt++) {
            uint32_t vb[4];
            uint32_t base = vb_base + (uint32_t)kt * (16 * 80) + v_lane_off;
            ldsm_x4_t(vb, base);
            mma_bf16(o[0], ap[kt], vb);
            mma_bf16(o[1], ap[kt], vb + 2);
            ldsm_x4_t(vb, base + 32);
            mma_bf16(o[2], ap[kt], vb);
            mma_bf16(o[3], ap[kt], vb + 2);
        }

        if (t < 31) { mw_lo = mw_lo_n; mw_hi = mw_hi_n; }
        __syncthreads();
    }

    ls0 += __shfl_xor_sync(0xFFFFFFFFu, ls0, 1);
    ls0 += __shfl_xor_sync(0xFFFFFFFFu, ls0, 2);
    ls1 += __shfl_xor_sync(0xFFFFFFFFu, ls1, 1);
    ls1 += __shfl_xor_sync(0xFFFFFFFFu, ls1, 2);
    float inv0 = 1.f / ls0, inv1 = 1.f / ls1;

    __nv_bfloat16* dst0 = g_attb + (size_t)row0 * DD + h * HD + 2 * tig;
    __nv_bfloat16* dst1 = dst0 + 8 * DD;
#pragma unroll
    for (int v = 0; v < 4; v++) {
        *(uint32_t*)(dst0 + v * 8) = pack_bf16x2(o[v][0] * inv0, o[v][1] * inv0);
        *(uint32_t*)(dst1 + v * 8) = pack_bf16x2(o[v][2] * inv1, o[v][3] * inv1);
    }
}

// ================= 6. residual + LayerNorm (warp-shuffle) =================
__global__ void ln_kernel(const float* __restrict__ tmp,
                          const float* __restrict__ x,
                          const float* __restrict__ w,
                          const float* __restrict__ b,
                          float* __restrict__ out) {
    int n = blockIdx.x;
    int tid = threadIdx.x;  // 256 == DD
    int wid = tid >> 5, lane = tid & 31;
    float v = tmp[n * DD + tid] + x[n * DD + tid];
    float s1 = v, s2 = v * v;
#pragma unroll
    for (int o = 16; o > 0; o >>= 1) {
        s1 += __shfl_xor_sync(0xFFFFFFFFu, s1, o);
        s2 += __shfl_xor_sync(0xFFFFFFFFu, s2, o);
    }
    __shared__ float a1[8], a2[8];
    if (lane == 0) { a1[wid] = s1; a2[wid] = s2; }
    __syncthreads();
    float t1 = 0.f, t2 = 0.f;
#pragma unroll
    for (int i = 0; i < 8; i++) { t1 += a1[i]; t2 += a2[i]; }
    float mu = t1 * (1.f / 256.f);
    float var = t2 * (1.f / 256.f) - mu * mu;
    float inv = rsqrtf(var + 1e-5f);
    out[n * DD + tid] = (v - mu) * inv * w[tid] + b[tid];
}

// ================= launch =================
extern "C" void kernel_launch(void* const* d_in, const int* in_sizes, int n_in,
                              void* d_out, int out_size) {
    const float* x   = (const float*)d_in[0];
    const int*   ei  = (const int*)d_in[1];
    const float* Wq  = (const float*)d_in[2];
    const float* bq  = (const float*)d_in[3];
    const float* Wk  = (const float*)d_in[4];
    const float* bk  = (const float*)d_in[5];
    const float* Wv  = (const float*)d_in[6];
    const float* bv  = (const float*)d_in[7];
    const float* Wo  = (const float*)d_in[8];
    const float* bo  = (const float*)d_in[9];
    const float* lnw = (const float*)d_in[10];
    const float* lnb = (const float*)d_in[11];
    float* out = (float*)d_out;

    float* gT;
    cudaGetSymbolAddress((void**)&gT, g_tmp);

    // casts + mask pipeline
    cast_kernel<<<(NN * DD + 4 * DD * DD) / 1024, 256>>>(x, Wq, Wk, Wv, Wo);
    adj_init_kernel<<<(NN * NWORDS) / 256, 256>>>();
    edge_kernel<<<EE / 128, 128>>>(ei);
    mask_kernel<<<NN, NWORDS>>>();

    // QKV projections (tensor core; Q/K fp8 out, V bf16 out)
    qkv_gemm_kernel<<<dim3(DD / 128, NN / 64, 3), 128>>>(bq, bk, bv);

    // tensor-core attention (fp8 QK^T, bf16 PV)
    attn_kernel<<<dim3(NN / 128, HH), 256>>>();

    // output projection (tensor core, fp32 out) + residual + LN
    wo_gemm_kernel<<<dim3(DD / 128, NN / 64), 128>>>(bo);
    ln_kernel<<<NN, 256>>>(gT, x, lnw, lnb, out);
}

// round 8
// speedup vs baseline: 1.0979x; 1.0979x over previous
#include <cuda_runtime.h>
#include <cuda_bf16.h>
#include <cuda_fp16.h>
#include <math.h>
#include <stdint.h>

// ---------------- problem constants ----------------
#define NN 4096
#define DD 256
#define HH 8
#define HD 32
#define EE 65536
#define NWORDS 128
// (1/sqrt(32)) * log2(e): folded into Q so softmax weight = exp2(S)
#define QSCALE 0.25503486f

// ---------------- scratch globals (no allocs allowed) ----------------
__device__ uint32_t g_adj[NN * NWORDS];
__device__ uint32_t g_mask[NN * NWORDS];
__device__ __nv_bfloat16 g_xb[NN * DD];
__device__ __nv_bfloat16 g_Wb[4 * DD * DD];   // Wq, Wk, Wv, Wo (bf16)
__device__ __half g_Qh[NN * DD];              // fp16, pre-scaled by QSCALE
__device__ __half g_Kh[NN * DD];
__device__ __half g_Vh[NN * DD];
__device__ __nv_bfloat16 g_attb[NN * DD];     // attention output (bf16)
__device__ float g_tmp[NN * DD];

// ---------------- PTX helpers ----------------
__device__ __forceinline__ uint32_t smem_u32(const void* p) {
    uint32_t a;
    asm("{ .reg .u64 t; cvta.to.shared.u64 t, %1; cvt.u32.u64 %0, t; }"
        : "=r"(a) : "l"(p));
    return a;
}
__device__ __forceinline__ uint32_t pack_bf16x2(float lo, float hi) {
    uint32_t r;
    asm("cvt.rn.bf16x2.f32 %0, %1, %2;" : "=r"(r) : "f"(hi), "f"(lo));
    return r;
}
__device__ __forceinline__ uint32_t pack_f16x2(float lo, float hi) {
    uint32_t r;
    asm("cvt.rn.f16x2.f32 %0, %1, %2;" : "=r"(r) : "f"(hi), "f"(lo));
    return r;
}
__device__ __forceinline__ uint32_t ex2_f16x2(uint32_t x) {
    uint32_t y;
    asm("ex2.approx.f16x2 %0, %1;" : "=r"(y) : "r"(x));
    return y;
}
__device__ __forceinline__ uint32_t hadd2(uint32_t a, uint32_t b) {
    uint32_t d;
    asm("add.rn.f16x2 %0, %1, %2;" : "=r"(d) : "r"(a), "r"(b));
    return d;
}
__device__ __forceinline__ float2 h2_to_f2(uint32_t u) {
    __half2 h = *reinterpret_cast<__half2*>(&u);
    return __half22float2(h);
}
__device__ __forceinline__ void ldsm_x4(uint32_t* r, uint32_t addr) {
    asm volatile("ldmatrix.sync.aligned.m8n8.x4.shared.b16 {%0,%1,%2,%3}, [%4];"
        : "=r"(r[0]), "=r"(r[1]), "=r"(r[2]), "=r"(r[3]) : "r"(addr));
}
__device__ __forceinline__ void ldsm_x4_t(uint32_t* r, uint32_t addr) {
    asm volatile("ldmatrix.sync.aligned.m8n8.x4.trans.shared.b16 {%0,%1,%2,%3}, [%4];"
        : "=r"(r[0]), "=r"(r[1]), "=r"(r[2]), "=r"(r[3]) : "r"(addr));
}
__device__ __forceinline__ void mma_bf16(float* c, const uint32_t* a, const uint32_t* b) {
    asm volatile(
        "mma.sync.aligned.m16n8k16.row.col.f32.bf16.bf16.f32 "
        "{%0,%1,%2,%3}, {%4,%5,%6,%7}, {%8,%9}, {%0,%1,%2,%3};"
        : "+f"(c[0]), "+f"(c[1]), "+f"(c[2]), "+f"(c[3])
        : "r"(a[0]), "r"(a[1]), "r"(a[2]), "r"(a[3]), "r"(b[0]), "r"(b[1]));
}
// fp16 in, fp16 accumulate (D packed f16x2: d0 = row g cols {2t,2t+1}, d1 = row g+8)
__device__ __forceinline__ void mma_h(uint32_t* d, const uint32_t* a, const uint32_t* b) {
    asm volatile(
        "mma.sync.aligned.m16n8k16.row.col.f16.f16.f16.f16 "
        "{%0,%1}, {%2,%3,%4,%5}, {%6,%7}, {%0,%1};"
        : "+r"(d[0]), "+r"(d[1])
        : "r"(a[0]), "r"(a[1]), "r"(a[2]), "r"(a[3]), "r"(b[0]), "r"(b[1]));
}
__device__ __forceinline__ void cp16(uint32_t dst, const void* src) {
    asm volatile("cp.async.cg.shared.global [%0], [%1], 16;" :: "r"(dst), "l"(src));
}
#define CP_COMMIT() asm volatile("cp.async.commit_group;" ::: "memory")
#define CP_WAIT(n)  asm volatile("cp.async.wait_group %0;" :: "n"(n) : "memory")

// ================= 0. bf16 casts (x + 4 weights, one launch) =================
__global__ void cast_kernel(const float* __restrict__ x,
                            const float* __restrict__ Wq, const float* __restrict__ Wk,
                            const float* __restrict__ Wv, const float* __restrict__ Wo) {
    int i = (blockIdx.x * 256 + threadIdx.x) * 4;
    const float* src;
    __nv_bfloat16* dst;
    if (i < NN * DD) {
        src = x + i; dst = g_xb + i;
    } else {
        int j = i - NN * DD;
        int w = j >> 16;
        int o = j & 65535;
        src = ((w == 0) ? Wq : (w == 1) ? Wk : (w == 2) ? Wv : Wo) + o;
        dst = g_Wb + w * (DD * DD) + o;
    }
    float4 v = *(const float4*)src;
    *(uint2*)dst = make_uint2(pack_bf16x2(v.x, v.y), pack_bf16x2(v.z, v.w));
}

// ================= 1. adjacency init (zero + self loops) =================
__global__ void adj_init_kernel() {
    int idx = blockIdx.x * blockDim.x + threadIdx.x;
    int n = idx >> 7, w = idx & 127;
    uint32_t v = 0;
    if (w == (n >> 5)) v = 1u << (n & 31);
    g_adj[idx] = v;
}

// ================= 2. scatter edges (undirected, 2 edges/thread) =========
__global__ void edge_kernel(const int* __restrict__ ei) {
    int e = (blockIdx.x * blockDim.x + threadIdx.x) * 2;
    if (e >= EE) return;
    uint2 s2 = *(const uint2*)(ei + e);
    uint2 d2 = *(const uint2*)(ei + EE + e);
    atomicOr(&g_adj[s2.x * NWORDS + (d2.x >> 5)], 1u << (d2.x & 31));
    atomicOr(&g_adj[d2.x * NWORDS + (s2.x >> 5)], 1u << (s2.x & 31));
    atomicOr(&g_adj[s2.y * NWORDS + (d2.y >> 5)], 1u << (d2.y & 31));
    atomicOr(&g_adj[d2.y * NWORDS + (s2.y >> 5)], 1u << (s2.y & 31));
}

// ================= 3. reach-2 mask (list build + uint4 row ORs) ===========
__global__ void mask_kernel() {
    int n = blockIdx.x;
    int tid = threadIdx.x;  // 128
    __shared__ uint16_t nbr[1024];
    __shared__ int cnt;
    if (tid == 0) cnt = 0;
    __syncthreads();
    // phase 1: each thread scans its own word, appends set bits
    uint32_t bits = g_adj[n * NWORDS + tid];
    while (bits) {
        int b = __ffs(bits) - 1;
        bits &= bits - 1;
        int i = atomicAdd(&cnt, 1);
        nbr[i] = (uint16_t)((tid << 5) + b);
    }
    __syncthreads();
    // phase 2: 32 threads, uint4 per row (4-deep MLP)
    if (tid < 32) {
        int c = cnt;
        uint4 acc = make_uint4(0, 0, 0, 0);
        int i = 0;
        for (; i + 4 <= c; i += 4) {
            uint4 a0 = *(const uint4*)(g_adj + (int)nbr[i + 0] * NWORDS + tid * 4);
            uint4 a1 = *(const uint4*)(g_adj + (int)nbr[i + 1] * NWORDS + tid * 4);
            uint4 a2 = *(const uint4*)(g_adj + (int)nbr[i + 2] * NWORDS + tid * 4);
            uint4 a3 = *(const uint4*)(g_adj + (int)nbr[i + 3] * NWORDS + tid * 4);
            acc.x |= a0.x | a1.x | a2.x | a3.x;
            acc.y |= a0.y | a1.y | a2.y | a3.y;
            acc.z |= a0.z | a1.z | a2.z | a3.z;
            acc.w |= a0.w | a1.w | a2.w | a3.w;
        }
        for (; i < c; i++) {
            uint4 a0 = *(const uint4*)(g_adj + (int)nbr[i] * NWORDS + tid * 4);
            acc.x |= a0.x; acc.y |= a0.y; acc.z |= a0.z; acc.w |= a0.w;
        }
        *(uint4*)(g_mask + n * NWORDS + tid * 4) = acc;
    }
}

// ================= 4. bf16 tensor-core GEMM =================
// C[M=4096, N=256] = A[4096,256]@W[256,256] + bias. CTA tile 64x128, BK=32.
// MODE: 0 = f16 out (scaled), 1 = f32 out
template <int MODE>
__device__ __forceinline__ void gemm_core(const __nv_bfloat16* __restrict__ A,
                                          const __nv_bfloat16* __restrict__ W,
                                          const float* __restrict__ bias,
                                          void* __restrict__ Cv, float scale) {
    __shared__ __nv_bfloat16 sA[2][64 * 40];
    __shared__ __nv_bfloat16 sB[2][32 * 136];

    const int tid = threadIdx.x;
    const int wid = tid >> 5;
    const int lane = tid & 31;
    const int m0 = blockIdx.y * 64;
    const int n0 = blockIdx.x * 128;

    const uint32_t aA = smem_u32(sA);
    const uint32_t aB = smem_u32(sB);
    const char* Abase = (const char*)A + (size_t)m0 * (DD * 2);
    const char* Bbase = (const char*)W + (size_t)n0 * 2;

    {
#pragma unroll
        for (int j = 0; j < 2; j++) {
            int t = tid + j * 128;
            int r = t >> 2, c = t & 3;
            cp16(aA + r * 80 + c * 16, Abase + (size_t)r * 512 + c * 16);
        }
#pragma unroll
        for (int j = 0; j < 4; j++) {
            int t = tid + j * 128;
            int r = t >> 4, c = t & 15;
            cp16(aB + r * 272 + c * 16, Bbase + (size_t)r * 512 + c * 16);
        }
        CP_COMMIT();
    }

    float acc[16][4];
#pragma unroll
    for (int j = 0; j < 16; j++)
        acc[j][0] = acc[j][1] = acc[j][2] = acc[j][3] = 0.f;

    const int m = lane >> 3, rr = lane & 7;
    const uint32_t a_off = (uint32_t)((wid * 16 + (m & 1) * 8 + rr) * 80 + (m >> 1) * 16);
    const uint32_t b_lane = (uint32_t)(((lane >> 3) & 1) * 8 * 272 + (lane & 7) * 272 +
                                       (lane >> 4) * 16);

    for (int t = 0; t < 8; t++) {
        if (t < 7) {
            int nb = (t + 1) & 1;
            uint32_t dA = aA + (uint32_t)nb * 5120;
            uint32_t dB = aB + (uint32_t)nb * 8704;
            const char* As = Abase + (size_t)(t + 1) * 64;
            const char* Bs = Bbase + (size_t)(t + 1) * 32 * 512;
#pragma unroll
            for (int j = 0; j < 2; j++) {
                int u = tid + j * 128;
                int r = u >> 2, c = u & 3;
                cp16(dA + r * 80 + c * 16, As + (size_t)r * 512 + c * 16);
            }
#pragma unroll
            for (int j = 0; j < 4; j++) {
                int u = tid + j * 128;
                int r = u >> 4, c = u & 15;
                cp16(dB + r * 272 + c * 16, Bs + (size_t)r * 512 + c * 16);
            }
            CP_COMMIT();
            CP_WAIT(1);
        } else {
            CP_WAIT(0);
        }
        __syncthreads();

        const uint32_t bufA = aA + (uint32_t)(t & 1) * 5120;
        const uint32_t bufB = aB + (uint32_t)(t & 1) * 8704;

        uint32_t aq[2][4];
        ldsm_x4(aq[0], bufA + a_off);
        ldsm_x4(aq[1], bufA + a_off + 32);

#pragma unroll
        for (int ks = 0; ks < 2; ks++) {
#pragma unroll
            for (int j = 0; j < 8; j++) {
                uint32_t vb[4];
                ldsm_x4_t(vb, bufB + (uint32_t)(ks * 16 * 272 + j * 32) + b_lane);
                mma_bf16(acc[2 * j],     aq[ks], vb);
                mma_bf16(acc[2 * j + 1], aq[ks], vb + 2);
            }
        }
        __syncthreads();
    }

    const int gg = lane >> 2, tig = lane & 3;
    const int r0 = m0 + wid * 16 + gg;
#pragma unroll
    for (int j = 0; j < 16; j++) {
        int col = n0 + j * 8 + 2 * tig;
        float2 b2 = __ldg((const float2*)(bias + col));
        if (MODE == 1) {
            float* Cf = (float*)Cv;
            *(float2*)(Cf + (size_t)r0 * DD + col) =
                make_float2(acc[j][0] + b2.x, acc[j][1] + b2.y);
            *(float2*)(Cf + (size_t)(r0 + 8) * DD + col) =
                make_float2(acc[j][2] + b2.x, acc[j][3] + b2.y);
        } else {
            __half* Ch = (__half*)Cv;
            *(uint32_t*)(Ch + (size_t)r0 * DD + col) =
                pack_f16x2((acc[j][0] + b2.x) * scale, (acc[j][1] + b2.y) * scale);
            *(uint32_t*)(Ch + (size_t)(r0 + 8) * DD + col) =
                pack_f16x2((acc[j][2] + b2.x) * scale, (acc[j][3] + b2.y) * scale);
        }
    }
}

__global__ void __launch_bounds__(128) qkv_gemm_kernel(const float* __restrict__ bq,
                                                       const float* __restrict__ bk,
                                                       const float* __restrict__ bv) {
    int z = blockIdx.z;
    const float* bias = (z == 0) ? bq : (z == 1) ? bk : bv;
    __half* C = (z == 0) ? g_Qh : (z == 1) ? g_Kh : g_Vh;
    float scale = (z == 0) ? QSCALE : 1.f;
    gemm_core<0>(g_xb, g_Wb + (size_t)z * DD * DD, bias, C, scale);
}
__global__ void __launch_bounds__(128) wo_gemm_kernel(const float* __restrict__ bo) {
    gemm_core<1>(g_attb, g_Wb + (size_t)3 * DD * DD, bo, g_tmp, 1.f);
}

// ================= 5. mma.sync attention (fp16, f16 accumulators) =========
// CTA: 256 threads (8 warps), 128 queries, one head. 32 kv tiles of 128 keys.
// QK^T with f16 accum -> output arrives packed f16x2 == exp2 input == next
// A-fragment. PV with per-tile f16 accum flushed to fp32 master registers.
struct AttnSmemH {
    __half Qs[128 * 32];       // 8192 B (64B rows)
    __half Ks[2][128 * 40];    // 2 x 10240 B
    __half Vs[2][128 * 40];    // 2 x 10240 B
};                             // total 49152 B

__global__ void __launch_bounds__(256, 2) attn_kernel() {
    __shared__ AttnSmemH sm;
    const int tid = threadIdx.x;
    const int wid = tid >> 5;        // 0..7
    const int lane = tid & 31;
    const int h = blockIdx.y;
    const int q0 = blockIdx.x * 128;

    const uint32_t s_q = smem_u32(sm.Qs);
    const uint32_t s_k0 = smem_u32(sm.Ks[0]);
    const uint32_t s_v0 = smem_u32(sm.Vs[0]);

    const char* ksrc = (const char*)(g_Kh + h * HD);
    const char* vsrc = (const char*)(g_Vh + h * HD);

    // ---- prologue: Q + K0/V0 via cp.async ----
    {
        const char* qsrc = (const char*)(g_Qh + (size_t)q0 * DD + h * HD);
#pragma unroll
        for (int j = 0; j < 2; j++) {
            int chunk = tid + j * 256;
            int r = chunk >> 2, c = chunk & 3;
            cp16(s_q + (uint32_t)(r * 64 + c * 16), qsrc + (size_t)r * 512 + c * 16);
        }
#pragma unroll
        for (int j = 0; j < 2; j++) {
            int chunk = tid + j * 256;
            int r = chunk >> 2, c = chunk & 3;
            uint32_t off = (uint32_t)(r * 80 + c * 16);
            size_t gs = (size_t)r * 512 + c * 16;
            cp16(s_k0 + off, ksrc + gs);
            cp16(s_v0 + off, vsrc + gs);
        }
        CP_COMMIT();
    }

    const int wq0 = wid * 16;
    const int g = lane >> 2, tig = lane & 3;
    const int row0 = q0 + wq0 + g;

    uint4 mw_lo = *(const uint4*)(g_mask + (size_t)row0 * NWORDS);
    uint4 mw_hi = *(const uint4*)(g_mask + (size_t)(row0 + 8) * NWORDS);

    CP_WAIT(0);
    __syncthreads();

    uint32_t aq[2][4];
    {
        int m = lane >> 3, rr = lane & 7;
        uint32_t base = s_q + (uint32_t)((wq0 + (m & 1) * 8 + rr) * 64 + (m >> 1) * 16);
        ldsm_x4(aq[0], base);
        ldsm_x4(aq[1], base + 32);
    }

    float o[4][4];
#pragma unroll
    for (int v = 0; v < 4; v++)
#pragma unroll
        for (int i = 0; i < 4; i++) o[v][i] = 0.f;
    float ls0 = 0.f, ls1 = 0.f;

    const uint32_t k_lane_off = (uint32_t)((lane & 7) * 80 + (lane >> 3) * 16);
    const uint32_t v_lane_off = (uint32_t)(((lane >> 3) & 1) * 8 * 80 + (lane & 7) * 80 +
                                           (lane >> 4) * 16);

    for (int t = 0; t < 32; t++) {
        int buf = t & 1;
        uint4 mw_lo_n, mw_hi_n;
        if (t < 31) {
            mw_lo_n = *(const uint4*)(g_mask + (size_t)row0 * NWORDS + (t + 1) * 4);
            mw_hi_n = *(const uint4*)(g_mask + (size_t)(row0 + 8) * NWORDS + (t + 1) * 4);
            int nb = (t + 1) & 1;
            uint32_t skb = s_k0 + (uint32_t)nb * 10240;
            uint32_t svb = s_v0 + (uint32_t)nb * 10240;
            size_t tb = (size_t)(t + 1) * 128 * 512;
#pragma unroll
            for (int j = 0; j < 2; j++) {
                int chunk = tid + j * 256;
                int r = chunk >> 2, c = chunk & 3;
                uint32_t off = (uint32_t)(r * 80 + c * 16);
                size_t gs = tb + (size_t)r * 512 + c * 16;
                cp16(skb + off, ksrc + gs);
                cp16(svb + off, vsrc + gs);
            }
            CP_COMMIT();
            CP_WAIT(1);
        } else {
            CP_WAIT(0);
        }
        __syncthreads();

        const uint32_t kb_base = s_k0 + (uint32_t)buf * 10240;
        const uint32_t vb_base = s_v0 + (uint32_t)buf * 10240;
        const uint32_t mwl[4] = {mw_lo.x, mw_lo.y, mw_lo.z, mw_lo.w};
        const uint32_t mwh[4] = {mw_hi.x, mw_hi.y, mw_hi.z, mw_hi.w};

        uint32_t ap[8][4];
        uint32_t acc01 = 0, acc23 = 0;   // per-tile f16x2 row-sum accumulators
#pragma unroll
        for (int qd = 0; qd < 4; qd++) {
            uint32_t kb[4][4];
#pragma unroll
            for (int nt = 0; nt < 4; nt++)
                ldsm_x4(kb[nt], kb_base + (uint32_t)((qd * 4 + nt) * (8 * 80)) + k_lane_off);
            uint32_t w0 = mwl[qd] >> (2 * tig);
            uint32_t w1 = mwh[qd] >> (2 * tig);
#pragma unroll
            for (int nt = 0; nt < 4; nt++) {
                uint32_t sd[2] = {0u, 0u};
                mma_h(sd, aq[0], kb[nt]);
                mma_h(sd, aq[1], kb[nt] + 2);
                uint32_t b0 = w0 >> (nt * 8), b1 = w1 >> (nt * 8);
                uint32_t m01 = ((b0 & 1u) ? 0x0000FFFFu : 0u) | ((b0 & 2u) ? 0xFFFF0000u : 0u);
                uint32_t m23 = ((b1 & 1u) ? 0x0000FFFFu : 0u) | ((b1 & 2u) ? 0xFFFF0000u : 0u);
                uint32_t p01 = ex2_f16x2(sd[0]) & m01;
                uint32_t p23 = ex2_f16x2(sd[1]) & m23;
                acc01 = hadd2(acc01, p01);
                acc23 = hadd2(acc23, p23);
                int nth = qd * 4 + nt;
                ap[nth >> 1][(nth & 1) * 2 + 0] = p01;
                ap[nth >> 1][(nth & 1) * 2 + 1] = p23;
            }
        }
        // flush per-tile row sums to fp32
        {
            float2 f0 = h2_to_f2(acc01);
            float2 f1 = h2_to_f2(acc23);
            ls0 += f0.x + f0.y;
            ls1 += f1.x + f1.y;
        }

        // ---- O_tile = P @ V (f16 accum), flushed to fp32 master ----
        uint32_t of[4][2];
#pragma unroll
        for (int v = 0; v < 4; v++) { of[v][0] = 0u; of[v][1] = 0u; }
#pragma unroll
        for (int kt = 0; kt < 8; kt++) {
            uint32_t vb[4];
            uint32_t base = vb_base + (uint32_t)kt * (16 * 80) + v_lane_off;
            ldsm_x4_t(vb, base);
            mma_h(of[0], ap[kt], vb);
            mma_h(of[1], ap[kt], vb + 2);
            ldsm_x4_t(vb, base + 32);
            mma_h(of[2], ap[kt], vb);
            mma_h(of[3], ap[kt], vb + 2);
        }
#pragma unroll
        for (int v = 0; v < 4; v++) {
            float2 lo = h2_to_f2(of[v][0]);
            float2 hi = h2_to_f2(of[v][1]);
            o[v][0] += lo.x; o[v][1] += lo.y;
            o[v][2] += hi.x; o[v][3] += hi.y;
        }

        if (t < 31) { mw_lo = mw_lo_n; mw_hi = mw_hi_n; }
        __syncthreads();
    }

    // quad-reduce row sums (cols spread over tig lanes)
    ls0 += __shfl_xor_sync(0xFFFFFFFFu, ls0, 1);
    ls0 += __shfl_xor_sync(0xFFFFFFFFu, ls0, 2);
    ls1 += __shfl_xor_sync(0xFFFFFFFFu, ls1, 1);
    ls1 += __shfl_xor_sync(0xFFFFFFFFu, ls1, 2);
    float inv0 = 1.f / ls0, inv1 = 1.f / ls1;

    __nv_bfloat16* dst0 = g_attb + (size_t)row0 * DD + h * HD + 2 * tig;
    __nv_bfloat16* dst1 = dst0 + 8 * DD;
#pragma unroll
    for (int v = 0; v < 4; v++) {
        *(uint32_t*)(dst0 + v * 8) = pack_bf16x2(o[v][0] * inv0, o[v][1] * inv0);
        *(uint32_t*)(dst1 + v * 8) = pack_bf16x2(o[v][2] * inv1, o[v][3] * inv1);
    }
}

// ================= 6. residual + LayerNorm (warp-shuffle) =================
__global__ void ln_kernel(const float* __restrict__ tmp,
                          const float* __restrict__ x,
                          const float* __restrict__ w,
                          const float* __restrict__ b,
                          float* __restrict__ out) {
    int n = blockIdx.x;
    int tid = threadIdx.x;  // 256 == DD
    int wid = tid >> 5, lane = tid & 31;
    float v = tmp[n * DD + tid] + x[n * DD + tid];
    float s1 = v, s2 = v * v;
#pragma unroll
    for (int o = 16; o > 0; o >>= 1) {
        s1 += __shfl_xor_sync(0xFFFFFFFFu, s1, o);
        s2 += __shfl_xor_sync(0xFFFFFFFFu, s2, o);
    }
    __shared__ float a1[8], a2[8];
    if (lane == 0) { a1[wid] = s1; a2[wid] = s2; }
    __syncthreads();
    float t1 = 0.f, t2 = 0.f;
#pragma unroll
    for (int i = 0; i < 8; i++) { t1 += a1[i]; t2 += a2[i]; }
    float mu = t1 * (1.f / 256.f);
    float var = t2 * (1.f / 256.f) - mu * mu;
    float inv = rsqrtf(var + 1e-5f);
    out[n * DD + tid] = (v - mu) * inv * w[tid] + b[tid];
}

// ================= launch =================
extern "C" void kernel_launch(void* const* d_in, const int* in_sizes, int n_in,
                              void* d_out, int out_size) {
    const float* x   = (const float*)d_in[0];
    const int*   ei  = (const int*)d_in[1];
    const float* Wq  = (const float*)d_in[2];
    const float* bq  = (const float*)d_in[3];
    const float* Wk  = (const float*)d_in[4];
    const float* bk  = (const float*)d_in[5];
    const float* Wv  = (const float*)d_in[6];
    const float* bv  = (const float*)d_in[7];
    const float* Wo  = (const float*)d_in[8];
    const float* bo  = (const float*)d_in[9];
    const float* lnw = (const float*)d_in[10];
    const float* lnb = (const float*)d_in[11];
    float* out = (float*)d_out;

    float* gT;
    cudaGetSymbolAddress((void**)&gT, g_tmp);

    // casts + mask pipeline
    cast_kernel<<<(NN * DD + 4 * DD * DD) / 1024, 256>>>(x, Wq, Wk, Wv, Wo);
    adj_init_kernel<<<(NN * NWORDS) / 256, 256>>>();
    edge_kernel<<<EE / 256, 128>>>(ei);
    mask_kernel<<<NN, NWORDS>>>();

    // QKV projections (tensor core, fp16 out, Q pre-scaled)
    qkv_gemm_kernel<<<dim3(DD / 128, NN / 64, 3), 128>>>(bq, bk, bv);

    // tensor-core attention (fp16 data, f16 accumulators)
    attn_kernel<<<dim3(NN / 128, HH), 256>>>();

    // output projection (tensor core, fp32 out) + residual + LN
    wo_gemm_kernel<<<dim3(DD / 128, NN / 64), 128>>>(bo);
    ln_kernel<<<NN, 256>>>(gT, x, lnw, lnb, out);
}

// round 9
// speedup vs baseline: 1.1512x; 1.0486x over previous
#include <cuda_runtime.h>
#include <cuda_bf16.h>
#include <cuda_fp16.h>
#include <math.h>
#include <stdint.h>

// ---------------- problem constants ----------------
#define NN 4096
#define DD 256
#define HH 8
#define HD 32
#define EE 65536
#define NWORDS 128
// (1/sqrt(32)) * log2(e): folded into Q so softmax weight = exp2(S)
#define QSCALE 0.25503486f

// ---------------- scratch globals (no allocs allowed) ----------------
__device__ uint32_t g_adj[NN * NWORDS];
__device__ uint32_t g_mask[NN * NWORDS];
__device__ __nv_bfloat16 g_xb[NN * DD];
__device__ __nv_bfloat16 g_Wb[4 * DD * DD];   // Wq, Wk, Wv, Wo (bf16)
__device__ __half g_Qh[NN * DD];              // fp16, pre-scaled by QSCALE
__device__ __half g_Kh[NN * DD];
__device__ __half g_Vh[NN * DD];
__device__ __nv_bfloat16 g_attb[NN * DD];     // attention output (bf16)
__device__ float g_tmp[NN * DD];

// ---------------- PTX helpers ----------------
__device__ __forceinline__ uint32_t smem_u32(const void* p) {
    uint32_t a;
    asm("{ .reg .u64 t; cvta.to.shared.u64 t, %1; cvt.u32.u64 %0, t; }"
        : "=r"(a) : "l"(p));
    return a;
}
__device__ __forceinline__ uint32_t pack_bf16x2(float lo, float hi) {
    uint32_t r;
    asm("cvt.rn.bf16x2.f32 %0, %1, %2;" : "=r"(r) : "f"(hi), "f"(lo));
    return r;
}
__device__ __forceinline__ uint32_t pack_f16x2(float lo, float hi) {
    uint32_t r;
    asm("cvt.rn.f16x2.f32 %0, %1, %2;" : "=r"(r) : "f"(hi), "f"(lo));
    return r;
}
__device__ __forceinline__ uint32_t ex2_f16x2(uint32_t x) {
    uint32_t y;
    asm("ex2.approx.f16x2 %0, %1;" : "=r"(y) : "r"(x));
    return y;
}
__device__ __forceinline__ uint32_t hadd2(uint32_t a, uint32_t b) {
    uint32_t d;
    asm("add.rn.f16x2 %0, %1, %2;" : "=r"(d) : "r"(a), "r"(b));
    return d;
}
__device__ __forceinline__ uint32_t prmt(uint32_t a, uint32_t b, uint32_t sel) {
    uint32_t d;
    asm("prmt.b32 %0, %1, %2, %3;" : "=r"(d) : "r"(a), "r"(b), "r"(sel));
    return d;
}
__device__ __forceinline__ float2 h2_to_f2(uint32_t u) {
    __half2 h = *reinterpret_cast<__half2*>(&u);
    return __half22float2(h);
}
__device__ __forceinline__ void ldsm_x4(uint32_t* r, uint32_t addr) {
    asm volatile("ldmatrix.sync.aligned.m8n8.x4.shared.b16 {%0,%1,%2,%3}, [%4];"
        : "=r"(r[0]), "=r"(r[1]), "=r"(r[2]), "=r"(r[3]) : "r"(addr));
}
__device__ __forceinline__ void ldsm_x4_t(uint32_t* r, uint32_t addr) {
    asm volatile("ldmatrix.sync.aligned.m8n8.x4.trans.shared.b16 {%0,%1,%2,%3}, [%4];"
        : "=r"(r[0]), "=r"(r[1]), "=r"(r[2]), "=r"(r[3]) : "r"(addr));
}
__device__ __forceinline__ void mma_bf16(float* c, const uint32_t* a, const uint32_t* b) {
    asm volatile(
        "mma.sync.aligned.m16n8k16.row.col.f32.bf16.bf16.f32 "
        "{%0,%1,%2,%3}, {%4,%5,%6,%7}, {%8,%9}, {%0,%1,%2,%3};"
        : "+f"(c[0]), "+f"(c[1]), "+f"(c[2]), "+f"(c[3])
        : "r"(a[0]), "r"(a[1]), "r"(a[2]), "r"(a[3]), "r"(b[0]), "r"(b[1]));
}
// fp16 in, fp16 accumulate
__device__ __forceinline__ void mma_h(uint32_t* d, const uint32_t* a, const uint32_t* b) {
    asm volatile(
        "mma.sync.aligned.m16n8k16.row.col.f16.f16.f16.f16 "
        "{%0,%1}, {%2,%3,%4,%5}, {%6,%7}, {%0,%1};"
        : "+r"(d[0]), "+r"(d[1])
        : "r"(a[0]), "r"(a[1]), "r"(a[2]), "r"(a[3]), "r"(b[0]), "r"(b[1]));
}
__device__ __forceinline__ void cp16(uint32_t dst, const void* src) {
    asm volatile("cp.async.cg.shared.global [%0], [%1], 16;" :: "r"(dst), "l"(src));
}
#define CP_COMMIT() asm volatile("cp.async.commit_group;" ::: "memory")
#define CP_WAIT(n)  asm volatile("cp.async.wait_group %0;" :: "n"(n) : "memory")

// ================= 0. bf16 casts (x + 4 weights, one launch) =================
__global__ void cast_kernel(const float* __restrict__ x,
                            const float* __restrict__ Wq, const float* __restrict__ Wk,
                            const float* __restrict__ Wv, const float* __restrict__ Wo) {
    int i = (blockIdx.x * 256 + threadIdx.x) * 4;
    const float* src;
    __nv_bfloat16* dst;
    if (i < NN * DD) {
        src = x + i; dst = g_xb + i;
    } else {
        int j = i - NN * DD;
        int w = j >> 16;
        int o = j & 65535;
        src = ((w == 0) ? Wq : (w == 1) ? Wk : (w == 2) ? Wv : Wo) + o;
        dst = g_Wb + w * (DD * DD) + o;
    }
    float4 v = *(const float4*)src;
    *(uint2*)dst = make_uint2(pack_bf16x2(v.x, v.y), pack_bf16x2(v.z, v.w));
}

// ================= 1. adjacency init (zero + self loops) =================
__global__ void adj_init_kernel() {
    int idx = blockIdx.x * blockDim.x + threadIdx.x;
    int n = idx >> 7, w = idx & 127;
    uint32_t v = 0;
    if (w == (n >> 5)) v = 1u << (n & 31);
    g_adj[idx] = v;
}

// ================= 2. scatter edges (undirected, 2 edges/thread) =========
__global__ void edge_kernel(const int* __restrict__ ei) {
    int e = (blockIdx.x * blockDim.x + threadIdx.x) * 2;
    if (e >= EE) return;
    uint2 s2 = *(const uint2*)(ei + e);
    uint2 d2 = *(const uint2*)(ei + EE + e);
    atomicOr(&g_adj[s2.x * NWORDS + (d2.x >> 5)], 1u << (d2.x & 31));
    atomicOr(&g_adj[d2.x * NWORDS + (s2.x >> 5)], 1u << (s2.x & 31));
    atomicOr(&g_adj[s2.y * NWORDS + (d2.y >> 5)], 1u << (d2.y & 31));
    atomicOr(&g_adj[d2.y * NWORDS + (s2.y >> 5)], 1u << (s2.y & 31));
}

// ================= 3. reach-2 mask (2 nodes/block, scan list build) =======
__global__ void __launch_bounds__(256) mask_kernel() {
    int half = threadIdx.x >> 7;            // which node in this block
    int tid = threadIdx.x & 127;            // word index
    int lane = threadIdx.x & 31;
    int n = blockIdx.x * 2 + half;
    __shared__ uint16_t nbr[2][1024];
    __shared__ int cnt[2];
    if (threadIdx.x < 2) cnt[threadIdx.x] = 0;
    __syncthreads();

    // phase 1: ballot-scan list build (1 atomic per warp)
    uint32_t bits = g_adj[n * NWORDS + tid];
    int pc = __popc(bits);
    int pref = pc;
#pragma unroll
    for (int o = 1; o < 32; o <<= 1) {
        int v = __shfl_up_sync(0xFFFFFFFFu, pref, o);
        if (lane >= o) pref += v;
    }
    int wtot = __shfl_sync(0xFFFFFFFFu, pref, 31);
    int wbase = 0;
    if (lane == 0) wbase = atomicAdd(&cnt[half], wtot);
    wbase = __shfl_sync(0xFFFFFFFFu, wbase, 0);
    int off = wbase + pref - pc;
    uint32_t bb = bits;
    while (bb) {
        int b = __ffs(bb) - 1;
        bb &= bb - 1;
        nbr[half][off++] = (uint16_t)((tid << 5) + b);
    }
    __syncthreads();

    // phase 2: OR neighbor rows, 8-deep MLP
    int c = cnt[half];
    uint32_t acc = 0;
    int i = 0;
    for (; i + 8 <= c; i += 8) {
        uint32_t a0 = g_adj[(int)nbr[half][i + 0] * NWORDS + tid];
        uint32_t a1 = g_adj[(int)nbr[half][i + 1] * NWORDS + tid];
        uint32_t a2 = g_adj[(int)nbr[half][i + 2] * NWORDS + tid];
        uint32_t a3 = g_adj[(int)nbr[half][i + 3] * NWORDS + tid];
        uint32_t a4 = g_adj[(int)nbr[half][i + 4] * NWORDS + tid];
        uint32_t a5 = g_adj[(int)nbr[half][i + 5] * NWORDS + tid];
        uint32_t a6 = g_adj[(int)nbr[half][i + 6] * NWORDS + tid];
        uint32_t a7 = g_adj[(int)nbr[half][i + 7] * NWORDS + tid];
        acc |= ((a0 | a1) | (a2 | a3)) | ((a4 | a5) | (a6 | a7));
    }
    for (; i < c; i++)
        acc |= g_adj[(int)nbr[half][i] * NWORDS + tid];
    g_mask[n * NWORDS + tid] = acc;
}

// ================= 4. bf16 tensor-core GEMM =================
// C[M=4096, N=256] = A[4096,256]@W[256,256] + bias. CTA tile 64x128, BK=32.
// MODE: 0 = f16 out (scaled), 1 = f32 out
template <int MODE>
__device__ __forceinline__ void gemm_core(const __nv_bfloat16* __restrict__ A,
                                          const __nv_bfloat16* __restrict__ W,
                                          const float* __restrict__ bias,
                                          void* __restrict__ Cv, float scale) {
    __shared__ __nv_bfloat16 sA[2][64 * 40];
    __shared__ __nv_bfloat16 sB[2][32 * 136];

    const int tid = threadIdx.x;
    const int wid = tid >> 5;
    const int lane = tid & 31;
    const int m0 = blockIdx.y * 64;
    const int n0 = blockIdx.x * 128;

    const uint32_t aA = smem_u32(sA);
    const uint32_t aB = smem_u32(sB);
    const char* Abase = (const char*)A + (size_t)m0 * (DD * 2);
    const char* Bbase = (const char*)W + (size_t)n0 * 2;

    {
#pragma unroll
        for (int j = 0; j < 2; j++) {
            int t = tid + j * 128;
            int r = t >> 2, c = t & 3;
            cp16(aA + r * 80 + c * 16, Abase + (size_t)r * 512 + c * 16);
        }
#pragma unroll
        for (int j = 0; j < 4; j++) {
            int t = tid + j * 128;
            int r = t >> 4, c = t & 15;
            cp16(aB + r * 272 + c * 16, Bbase + (size_t)r * 512 + c * 16);
        }
        CP_COMMIT();
    }

    float acc[16][4];
#pragma unroll
    for (int j = 0; j < 16; j++)
        acc[j][0] = acc[j][1] = acc[j][2] = acc[j][3] = 0.f;

    const int m = lane >> 3, rr = lane & 7;
    const uint32_t a_off = (uint32_t)((wid * 16 + (m & 1) * 8 + rr) * 80 + (m >> 1) * 16);
    const uint32_t b_lane = (uint32_t)(((lane >> 3) & 1) * 8 * 272 + (lane & 7) * 272 +
                                       (lane >> 4) * 16);

    for (int t = 0; t < 8; t++) {
        if (t < 7) {
            int nb = (t + 1) & 1;
            uint32_t dA = aA + (uint32_t)nb * 5120;
            uint32_t dB = aB + (uint32_t)nb * 8704;
            const char* As = Abase + (size_t)(t + 1) * 64;
            const char* Bs = Bbase + (size_t)(t + 1) * 32 * 512;
#pragma unroll
            for (int j = 0; j < 2; j++) {
                int u = tid + j * 128;
                int r = u >> 2, c = u & 3;
                cp16(dA + r * 80 + c * 16, As + (size_t)r * 512 + c * 16);
            }
#pragma unroll
            for (int j = 0; j < 4; j++) {
                int u = tid + j * 128;
                int r = u >> 4, c = u & 15;
                cp16(dB + r * 272 + c * 16, Bs + (size_t)r * 512 + c * 16);
            }
            CP_COMMIT();
            CP_WAIT(1);
        } else {
            CP_WAIT(0);
        }
        __syncthreads();

        const uint32_t bufA = aA + (uint32_t)(t & 1) * 5120;
        const uint32_t bufB = aB + (uint32_t)(t & 1) * 8704;

        uint32_t aq[2][4];
        ldsm_x4(aq[0], bufA + a_off);
        ldsm_x4(aq[1], bufA + a_off + 32);

#pragma unroll
        for (int ks = 0; ks < 2; ks++) {
#pragma unroll
            for (int j = 0; j < 8; j++) {
                uint32_t vb[4];
                ldsm_x4_t(vb, bufB + (uint32_t)(ks * 16 * 272 + j * 32) + b_lane);
                mma_bf16(acc[2 * j],     aq[ks], vb);
                mma_bf16(acc[2 * j + 1], aq[ks], vb + 2);
            }
        }
        __syncthreads();
    }

    const int gg = lane >> 2, tig = lane & 3;
    const int r0 = m0 + wid * 16 + gg;
#pragma unroll
    for (int j = 0; j < 16; j++) {
        int col = n0 + j * 8 + 2 * tig;
        float2 b2 = __ldg((const float2*)(bias + col));
        if (MODE == 1) {
            float* Cf = (float*)Cv;
            *(float2*)(Cf + (size_t)r0 * DD + col) =
                make_float2(acc[j][0] + b2.x, acc[j][1] + b2.y);
            *(float2*)(Cf + (size_t)(r0 + 8) * DD + col) =
                make_float2(acc[j][2] + b2.x, acc[j][3] + b2.y);
        } else {
            __half* Ch = (__half*)Cv;
            *(uint32_t*)(Ch + (size_t)r0 * DD + col) =
                pack_f16x2((acc[j][0] + b2.x) * scale, (acc[j][1] + b2.y) * scale);
            *(uint32_t*)(Ch + (size_t)(r0 + 8) * DD + col) =
                pack_f16x2((acc[j][2] + b2.x) * scale, (acc[j][3] + b2.y) * scale);
        }
    }
}

__global__ void __launch_bounds__(128) qkv_gemm_kernel(const float* __restrict__ bq,
                                                       const float* __restrict__ bk,
                                                       const float* __restrict__ bv) {
    int z = blockIdx.z;
    const float* bias = (z == 0) ? bq : (z == 1) ? bk : bv;
    __half* C = (z == 0) ? g_Qh : (z == 1) ? g_Kh : g_Vh;
    float scale = (z == 0) ? QSCALE : 1.f;
    gemm_core<0>(g_xb, g_Wb + (size_t)z * DD * DD, bias, C, scale);
}
__global__ void __launch_bounds__(128) wo_gemm_kernel(const float* __restrict__ bo) {
    gemm_core<1>(g_attb, g_Wb + (size_t)3 * DD * DD, bo, g_tmp, 1.f);
}

// ================= 5. mma.sync attention (fp16, f16 accum, PRMT masks) ====
// CTA: 256 threads (8 warps), 128 queries, one head. 32 kv tiles of 128 keys.
struct AttnSmemH {
    __half Qs[128 * 32];       // 8192 B (64B rows)
    __half Ks[2][128 * 40];    // 2 x 10240 B
    __half Vs[2][128 * 40];    // 2 x 10240 B
};                             // total 49152 B

__global__ void __launch_bounds__(256, 2) attn_kernel() {
    __shared__ AttnSmemH sm;
    const int tid = threadIdx.x;
    const int wid = tid >> 5;        // 0..7
    const int lane = tid & 31;
    const int h = blockIdx.y;
    const int q0 = blockIdx.x * 128;

    const uint32_t s_q = smem_u32(sm.Qs);
    const uint32_t s_k0 = smem_u32(sm.Ks[0]);
    const uint32_t s_v0 = smem_u32(sm.Vs[0]);

    const char* ksrc = (const char*)(g_Kh + h * HD);
    const char* vsrc = (const char*)(g_Vh + h * HD);

    // ---- prologue: Q + K0/V0 via cp.async ----
    {
        const char* qsrc = (const char*)(g_Qh + (size_t)q0 * DD + h * HD);
#pragma unroll
        for (int j = 0; j < 2; j++) {
            int chunk = tid + j * 256;
            int r = chunk >> 2, c = chunk & 3;
            cp16(s_q + (uint32_t)(r * 64 + c * 16), qsrc + (size_t)r * 512 + c * 16);
        }
#pragma unroll
        for (int j = 0; j < 2; j++) {
            int chunk = tid + j * 256;
            int r = chunk >> 2, c = chunk & 3;
            uint32_t off = (uint32_t)(r * 80 + c * 16);
            size_t gs = (size_t)r * 512 + c * 16;
            cp16(s_k0 + off, ksrc + gs);
            cp16(s_v0 + off, vsrc + gs);
        }
        CP_COMMIT();
    }

    const int wq0 = wid * 16;
    const int g = lane >> 2, tig = lane & 3;
    const int row0 = q0 + wq0 + g;

    uint4 mw_lo = *(const uint4*)(g_mask + (size_t)row0 * NWORDS);
    uint4 mw_hi = *(const uint4*)(g_mask + (size_t)(row0 + 8) * NWORDS);

    CP_WAIT(0);
    __syncthreads();

    uint32_t aq[2][4];
    {
        int m = lane >> 3, rr = lane & 7;
        uint32_t base = s_q + (uint32_t)((wq0 + (m & 1) * 8 + rr) * 64 + (m >> 1) * 16);
        ldsm_x4(aq[0], base);
        ldsm_x4(aq[1], base + 32);
    }

    float o[4][4];
#pragma unroll
    for (int v = 0; v < 4; v++)
#pragma unroll
        for (int i = 0; i < 4; i++) o[v][i] = 0.f;
    float ls0 = 0.f, ls1 = 0.f;

    const uint32_t k_lane_off = (uint32_t)((lane & 7) * 80 + (lane >> 3) * 16);
    const uint32_t v_lane_off = (uint32_t)(((lane >> 3) & 1) * 8 * 80 + (lane & 7) * 80 +
                                           (lane >> 4) * 16);

    for (int t = 0; t < 32; t++) {
        int buf = t & 1;
        uint4 mw_lo_n, mw_hi_n;
        if (t < 31) {
            mw_lo_n = *(const uint4*)(g_mask + (size_t)row0 * NWORDS + (t + 1) * 4);
            mw_hi_n = *(const uint4*)(g_mask + (size_t)(row0 + 8) * NWORDS + (t + 1) * 4);
            int nb = (t + 1) & 1;
            uint32_t skb = s_k0 + (uint32_t)nb * 10240;
            uint32_t svb = s_v0 + (uint32_t)nb * 10240;
            size_t tb = (size_t)(t + 1) * 128 * 512;
#pragma unroll
            for (int j = 0; j < 2; j++) {
                int chunk = tid + j * 256;
                int r = chunk >> 2, c = chunk & 3;
                uint32_t off = (uint32_t)(r * 80 + c * 16);
                size_t gs = tb + (size_t)r * 512 + c * 16;
                cp16(skb + off, ksrc + gs);
                cp16(svb + off, vsrc + gs);
            }
            CP_COMMIT();
            CP_WAIT(1);
        } else {
            CP_WAIT(0);
        }
        __syncthreads();

        const uint32_t kb_base = s_k0 + (uint32_t)buf * 10240;
        const uint32_t vb_base = s_v0 + (uint32_t)buf * 10240;
        const uint32_t mwl[4] = {mw_lo.x, mw_lo.y, mw_lo.z, mw_lo.w};
        const uint32_t mwh[4] = {mw_hi.x, mw_hi.y, mw_hi.z, mw_hi.w};

        uint32_t ap[8][4];
        uint32_t acc01 = 0, acc23 = 0;   // per-tile f16x2 row-sum accumulators
#pragma unroll
        for (int qd = 0; qd < 4; qd++) {
            uint32_t kb[4][4];
#pragma unroll
            for (int nt = 0; nt < 4; nt++)
                ldsm_x4(kb[nt], kb_base + (uint32_t)((qd * 4 + nt) * (8 * 80)) + k_lane_off);
            // mask bits -> byte MSBs (once per quad); per n-tile: single PRMT
            uint32_t w0 = mwl[qd] >> (2 * tig);
            uint32_t w1 = mwh[qd] >> (2 * tig);
            uint32_t y1 = (w0 & 0x01010101u) << 7;
            uint32_t y2 = (w0 & 0x02020202u) << 6;
            uint32_t z1 = (w1 & 0x01010101u) << 7;
            uint32_t z2 = (w1 & 0x02020202u) << 6;
#pragma unroll
            for (int nt = 0; nt < 4; nt++) {
                uint32_t sd[2] = {0u, 0u};
                mma_h(sd, aq[0], kb[nt]);
                mma_h(sd, aq[1], kb[nt] + 2);
                // selector: bytes {8+nt,8+nt,12+nt,12+nt} sign-replicated
                uint32_t sel = 0xCC88u + (uint32_t)nt * 0x1111u;
                uint32_t p01 = ex2_f16x2(sd[0]) & prmt(y1, y2, sel);
                uint32_t p23 = ex2_f16x2(sd[1]) & prmt(z1, z2, sel);
                acc01 = hadd2(acc01, p01);
                acc23 = hadd2(acc23, p23);
                int nth = qd * 4 + nt;
                ap[nth >> 1][(nth & 1) * 2 + 0] = p01;
                ap[nth >> 1][(nth & 1) * 2 + 1] = p23;
            }
        }
        // flush per-tile row sums to fp32
        {
            float2 f0 = h2_to_f2(acc01);
            float2 f1 = h2_to_f2(acc23);
            ls0 += f0.x + f0.y;
            ls1 += f1.x + f1.y;
        }

        // ---- O_tile = P @ V (f16 accum), flushed to fp32 master ----
        uint32_t of[4][2];
#pragma unroll
        for (int v = 0; v < 4; v++) { of[v][0] = 0u; of[v][1] = 0u; }
#pragma unroll
        for (int kt = 0; kt < 8; kt++) {
            uint32_t vb[4];
            uint32_t base = vb_base + (uint32_t)kt * (16 * 80) + v_lane_off;
            ldsm_x4_t(vb, base);
            mma_h(of[0], ap[kt], vb);
            mma_h(of[1], ap[kt], vb + 2);
            ldsm_x4_t(vb, base + 32);
            mma_h(of[2], ap[kt], vb);
            mma_h(of[3], ap[kt], vb + 2);
        }
#pragma unroll
        for (int v = 0; v < 4; v++) {
            float2 lo = h2_to_f2(of[v][0]);
            float2 hi = h2_to_f2(of[v][1]);
            o[v][0] += lo.x; o[v][1] += lo.y;
            o[v][2] += hi.x; o[v][3] += hi.y;
        }

        if (t < 31) { mw_lo = mw_lo_n; mw_hi = mw_hi_n; }
        __syncthreads();
    }

    // quad-reduce row sums (cols spread over tig lanes)
    ls0 += __shfl_xor_sync(0xFFFFFFFFu, ls0, 1);
    ls0 += __shfl_xor_sync(0xFFFFFFFFu, ls0, 2);
    ls1 += __shfl_xor_sync(0xFFFFFFFFu, ls1, 1);
    ls1 += __shfl_xor_sync(0xFFFFFFFFu, ls1, 2);
    float inv0 = 1.f / ls0, inv1 = 1.f / ls1;

    __nv_bfloat16* dst0 = g_attb + (size_t)row0 * DD + h * HD + 2 * tig;
    __nv_bfloat16* dst1 = dst0 + 8 * DD;
#pragma unroll
    for (int v = 0; v < 4; v++) {
        *(uint32_t*)(dst0 + v * 8) = pack_bf16x2(o[v][0] * inv0, o[v][1] * inv0);
        *(uint32_t*)(dst1 + v * 8) = pack_bf16x2(o[v][2] * inv1, o[v][3] * inv1);
    }
}

// ================= 6. residual + LayerNorm (warp-shuffle) =================
__global__ void ln_kernel(const float* __restrict__ tmp,
                          const float* __restrict__ x,
                          const float* __restrict__ w,
                          const float* __restrict__ b,
                          float* __restrict__ out) {
    int n = blockIdx.x;
    int tid = threadIdx.x;  // 256 == DD
    int wid = tid >> 5, lane = tid & 31;
    float v = tmp[n * DD + tid] + x[n * DD + tid];
    float s1 = v, s2 = v * v;
#pragma unroll
    for (int o = 16; o > 0; o >>= 1) {
        s1 += __shfl_xor_sync(0xFFFFFFFFu, s1, o);
        s2 += __shfl_xor_sync(0xFFFFFFFFu, s2, o);
    }
    __shared__ float a1[8], a2[8];
    if (lane == 0) { a1[wid] = s1; a2[wid] = s2; }
    __syncthreads();
    float t1 = 0.f, t2 = 0.f;
#pragma unroll
    for (int i = 0; i < 8; i++) { t1 += a1[i]; t2 += a2[i]; }
    float mu = t1 * (1.f / 256.f);
    float var = t2 * (1.f / 256.f) - mu * mu;
    float inv = rsqrtf(var + 1e-5f);
    out[n * DD + tid] = (v - mu) * inv * w[tid] + b[tid];
}

// ================= launch =================
extern "C" void kernel_launch(void* const* d_in, const int* in_sizes, int n_in,
                              void* d_out, int out_size) {
    const float* x   = (const float*)d_in[0];
    const int*   ei  = (const int*)d_in[1];
    const float* Wq  = (const float*)d_in[2];
    const float* bq  = (const float*)d_in[3];
    const float* Wk  = (const float*)d_in[4];
    const float* bk  = (const float*)d_in[5];
    const float* Wv  = (const float*)d_in[6];
    const float* bv  = (const float*)d_in[7];
    const float* Wo  = (const float*)d_in[8];
    const float* bo  = (const float*)d_in[9];
    const float* lnw = (const float*)d_in[10];
    const float* lnb = (const float*)d_in[11];
    float* out = (float*)d_out;

    float* gT;
    cudaGetSymbolAddress((void**)&gT, g_tmp);

    // casts + mask pipeline
    cast_kernel<<<(NN * DD + 4 * DD * DD) / 1024, 256>>>(x, Wq, Wk, Wv, Wo);
    adj_init_kernel<<<(NN * NWORDS) / 256, 256>>>();
    edge_kernel<<<EE / 256, 128>>>(ei);
    mask_kernel<<<NN / 2, 256>>>();

    // QKV projections (tensor core, fp16 out, Q pre-scaled)
    qkv_gemm_kernel<<<dim3(DD / 128, NN / 64, 3), 128>>>(bq, bk, bv);

    // tensor-core attention (fp16 data, f16 accumulators)
    attn_kernel<<<dim3(NN / 128, HH), 256>>>();

    // output projection (tensor core, fp32 out) + residual + LN
    wo_gemm_kernel<<<dim3(DD / 128, NN / 64), 128>>>(bo);
    ln_kernel<<<NN, 256>>>(gT, x, lnw, lnb, out);
}